// round 5
// baseline (speedup 1.0000x reference)
#include <cuda_runtime.h>
#include <cstdint>

#define B_   256
#define T_   127
#define K_   128
#define H_   256
#define G4_  1024
#define BT_  (B_ * T_)       // 32512 = 508*64
#define CL_  8
#define MB_  16
#define HS_  32
#define NT_  512

__device__ float g_gx[(size_t)BT_ * G4_];    // [bt][row] x-gates + bias (133 MB)

__device__ __forceinline__ unsigned smem_u32(const void* p) {
    return (unsigned)__cvta_generic_to_shared(p);
}
__device__ __forceinline__ unsigned mapa_rank(unsigned a, unsigned r) {
    unsigned ra; asm("mapa.shared::cluster.u32 %0, %1, %2;" : "=r"(ra) : "r"(a), "r"(r));
    return ra;
}
__device__ __forceinline__ void st_cluster_f32(unsigned ra, float v) {
    asm volatile("st.shared::cluster.f32 [%0], %1;" :: "r"(ra), "f"(v) : "memory");
}
__device__ __forceinline__ void cl_arrive() {
    asm volatile("barrier.cluster.arrive.aligned;" ::: "memory");
}
__device__ __forceinline__ void cl_wait() {
    asm volatile("barrier.cluster.wait.aligned;" ::: "memory");
}
__device__ __forceinline__ float sigm(float x) { return 1.f / (1.f + __expf(-x)); }
__device__ __forceinline__ float ftanh(float x) { return 2.f / (1.f + __expf(-2.f * x)) - 1.f; }
__device__ __forceinline__ unsigned long long pack2(float v) {
    unsigned long long d; unsigned u = __float_as_uint(v);
    asm("mov.b64 %0, {%1, %1};" : "=l"(d) : "r"(u)); return d;
}
__device__ __forceinline__ void fma2(unsigned long long& a, unsigned long long w,
                                     unsigned long long x) {
    asm("fma.rn.f32x2 %0, %1, %2, %0;" : "+l"(a) : "l"(w), "l"(x));
}
__device__ __forceinline__ float2 unpack2(unsigned long long a) {
    unsigned lo, hi; asm("mov.b64 {%0, %1}, %2;" : "=r"(lo), "=r"(hi) : "l"(a));
    return make_float2(__uint_as_float(lo), __uint_as_float(hi));
}

// ---------------- Kernel A: softmax alpha + weight output -------------------
__global__ void __launch_bounds__(128) k_alpha(const float* __restrict__ inp,
                                               const float* __restrict__ fc_w,
                                               float* __restrict__ out_w) {
    __shared__ float wx[T_];
    __shared__ float red[4];
    const int b = blockIdx.x, k = threadIdx.x;
    if (k < T_) wx[k] = fc_w[2 * H_ + k];
    __syncthreads();
    const float* ib = inp + (size_t)b * T_ * K_;
    float acc = 0.f;
#pragma unroll 4
    for (int t = 0; t < T_; t++) acc += ib[t * K_ + k] * wx[t];
    float m = acc;
#pragma unroll
    for (int o = 16; o; o >>= 1) m = fmaxf(m, __shfl_xor_sync(~0u, m, o));
    if ((k & 31) == 0) red[k >> 5] = m;
    __syncthreads();
    m = fmaxf(fmaxf(red[0], red[1]), fmaxf(red[2], red[3]));
    __syncthreads();
    float e = __expf(acc - m), s = e;
#pragma unroll
    for (int o = 16; o; o >>= 1) s += __shfl_xor_sync(~0u, s, o);
    if ((k & 31) == 0) red[k >> 5] = s;
    __syncthreads();
    s = red[0] + red[1] + red[2] + red[3];
    const float alpha = e / s;
    float* ob = out_w + (size_t)b * T_ * K_;
#pragma unroll 4
    for (int t = 0; t < T_; t++) ob[t * K_ + k] = alpha * ib[t * K_ + k];
}

// ---------------- Kernel X: g_gx = xw @ W_ih^T + bias -----------------------
// tile 64 bt x 128 rows; 512 thr = 128 r x 4 q (16 bt each)
#define XS_STR 68
#define WS_STR 132
#define GX_XS  (128 * XS_STR)
#define GX_WS  (128 * WS_STR)
#define GX_SMEMB ((GX_XS + GX_WS + 128) * 4)

__global__ void __launch_bounds__(NT_, 2) k_xgemm(const float* __restrict__ xw,
                                                  const float* __restrict__ W_ih,
                                                  const float* __restrict__ b_ih,
                                                  const float* __restrict__ b_hh) {
    extern __shared__ float s[];
    float* xs  = s;                    // [k][68]
    float* ws  = s + GX_XS;            // [k][132]
    float* bsm = ws + GX_WS;
    const int tid = threadIdx.x;
    const int mt = blockIdx.x >> 3, rt = blockIdx.x & 7;
    const int bt0 = mt * 64;

#pragma unroll
    for (int it = 0; it < 16; it++) {              // 8192 = 128k x 64b
        int idx = tid + NT_ * it;
        int k = idx & 127, b = idx >> 7;
        xs[k * XS_STR + b] = xw[(size_t)(bt0 + b) * K_ + k];
    }
#pragma unroll
    for (int it = 0; it < 32; it++) {              // 16384 = 128k x 128r
        int idx = tid + NT_ * it;
        int k = idx & 127, r = idx >> 7;
        ws[k * WS_STR + r] = W_ih[(rt * 128 + r) * K_ + k];
    }
    if (tid < 128) bsm[tid] = b_ih[rt * 128 + tid] + b_hh[rt * 128 + tid];
    __syncthreads();

    const int r = tid & 127, q = tid >> 7;
    const float* xq = xs + q * 16;
    unsigned long long A[8] = {0, 0, 0, 0, 0, 0, 0, 0};
#pragma unroll 4
    for (int k = 0; k < 128; k++) {
        unsigned long long w2 = pack2(ws[k * WS_STR + r]);
        const ulonglong2* xp = reinterpret_cast<const ulonglong2*>(xq + k * XS_STR);
        ulonglong2 x0 = xp[0], x1 = xp[1], x2 = xp[2], x3 = xp[3];
        fma2(A[0], w2, x0.x); fma2(A[1], w2, x0.y);
        fma2(A[2], w2, x1.x); fma2(A[3], w2, x1.y);
        fma2(A[4], w2, x2.x); fma2(A[5], w2, x2.y);
        fma2(A[6], w2, x3.x); fma2(A[7], w2, x3.y);
    }
    float bias = bsm[r];
    const size_t col = (size_t)rt * 128 + r;
#pragma unroll
    for (int j = 0; j < 8; j++) {
        float2 v = unpack2(A[j]);
        g_gx[(size_t)(bt0 + q * 16 + 2 * j)     * G4_ + col] = v.x + bias;
        g_gx[(size_t)(bt0 + q * 16 + 2 * j + 1) * G4_ + col] = v.y + bias;
    }
}

// ---------------- Kernel L: recurrence only (K=256 gemv) --------------------
#define OFF_WH  0                          // [256 n][128 r]
#define OFF_HT  (OFF_WH + 256 * 128)       // [2][256 n][20 m]
#define OFF_GB  (OFF_HT + 2 * 256 * 20)    // [2 nh][128 r][17]
#define L_SMEMB ((OFF_GB + 2 * 128 * 17) * 4)   // 189440 B

__global__ void __launch_bounds__(NT_, 1) __cluster_dims__(CL_, 1, 1)
k_lstm(const float* __restrict__ W_hh, float* __restrict__ out_h) {
    extern __shared__ float sm[];
    float* Wh = sm + OFF_WH;
    float* hT = sm + OFF_HT;
    float* gb = sm + OFF_GB;

    const int tid = threadIdx.x;
    unsigned rank; asm("mov.u32 %0, %%cluster_ctarank;" : "=r"(rank));
    const int b0 = (blockIdx.x / CL_) * MB_;

    // stage W_hh slice transposed: Wh[n*128 + rl] = W_hh[grow(rl)*H + n]
#pragma unroll
    for (int it = 0; it < 64; it++) {
        int idx = tid + NT_ * it;
        int n = idx & 255, rl = idx >> 8;
        int grow = (rl >> 5) * H_ + (int)rank * HS_ + (rl & 31);
        Wh[n * 128 + rl] = W_hh[grow * H_ + n];
    }
#pragma unroll
    for (int it = 0; it < 20; it++) hT[tid + NT_ * it] = 0.f;   // both buffers

    // gemv roles: r = gate row, mh = batch half, nh = n half
    const int r  = tid & 127;
    const int mh = (tid >> 7) & 1;
    const int nh = tid >> 8;
    const int grow_r = (r >> 5) * H_ + (int)rank * HS_ + (r & 31);
    const float* Wp = Wh + nh * (128 * 128) + r;
    float* gbp = gb + nh * (128 * 17) + r * 17 + mh * 8;

    // cell roles
    const int cjl = tid & 31, cm = tid >> 5;
    unsigned hdst[CL_];
    {
        unsigned la = smem_u32(&hT[((int)rank * HS_ + cjl) * 20 + cm]);
#pragma unroll
        for (unsigned pr = 0; pr < CL_; pr++) hdst[pr] = mapa_rank(la, pr);
    }
    float c_reg = 0.f;
    float* outp = out_h + (size_t)(b0 + cm) * T_ * H_ + (int)rank * HS_ + cjl;

    __syncthreads();
    cl_arrive();                    // publish zero-init / pair with first wait

    int p = 0;
    for (int t = 0; t < T_; t++) {
        // prefetch x-gates (coalesced; consumed after gemv)
        float gx0, gx1, gx2, gx3;
        {
            const int j0 = mh * 8 + nh * 4;
            const float* gp = g_gx + (size_t)((b0 + j0) * T_ + t) * G4_ + grow_r;
            const size_t st = (size_t)T_ * G4_;
            gx0 = gp[0]; gx1 = gp[st]; gx2 = gp[2 * st]; gx3 = gp[3 * st];
        }

        cl_wait();                  // prev-step h visible (acquire)

        // gemv over hT[p]: 128 n, 8 batches (4 f32x2 accumulators)
        const float* Hp = hT + p * 5120 + nh * (128 * 20) + mh * 8;
        unsigned long long A0 = 0, A1 = 0, A2 = 0, A3 = 0;
#pragma unroll 4
        for (int n = 0; n < 128; n++) {
            unsigned long long w2 = pack2(Wp[n * 128]);
            const ulonglong2* hp = reinterpret_cast<const ulonglong2*>(Hp + n * 20);
            ulonglong2 ha = hp[0], hb = hp[1];
            fma2(A0, w2, ha.x); fma2(A1, w2, ha.y);
            fma2(A2, w2, hb.x); fma2(A3, w2, hb.y);
        }
        float2 p0 = unpack2(A0), p1 = unpack2(A1), p2 = unpack2(A2), p3 = unpack2(A3);
        if (nh == 0) { p0.x += gx0; p0.y += gx1; p1.x += gx2; p1.y += gx3; }
        else         { p2.x += gx0; p2.y += gx1; p3.x += gx2; p3.y += gx3; }
        gbp[0] = p0.x; gbp[1] = p0.y; gbp[2] = p1.x; gbp[3] = p1.y;
        gbp[4] = p2.x; gbp[5] = p2.y; gbp[6] = p3.x; gbp[7] = p3.y;
        __syncthreads();

        // cell (conflict-free stride-17 reads; c in register)
        const float* g0 = gb;
        const float* g1 = gb + 128 * 17;
        float gi = g0[cjl * 17 + cm]        + g1[cjl * 17 + cm];
        float gf = g0[(32 + cjl) * 17 + cm] + g1[(32 + cjl) * 17 + cm];
        float gg = g0[(64 + cjl) * 17 + cm] + g1[(64 + cjl) * 17 + cm];
        float go = g0[(96 + cjl) * 17 + cm] + g1[(96 + cjl) * 17 + cm];
        c_reg = sigm(gf) * c_reg + sigm(gi) * ftanh(gg);
        float hn = sigm(go) * ftanh(c_reg);

        *outp = hn; outp += H_;                 // coalesced STG

        // broadcast h into hT[p^1] on all ranks
        unsigned off = (unsigned)((p ^ 1) * 5120 * 4);
#pragma unroll
        for (int pr = 0; pr < CL_; pr++) st_cluster_f32(hdst[pr] + off, hn);

        cl_arrive();                 // release h writes
        __syncthreads();             // gb safe to overwrite next step
        p ^= 1;
    }
    cl_wait();                       // balance final arrive
}

// ---------------- Launch -----------------------------------------------------
extern "C" void kernel_launch(void* const* d_in, const int* in_sizes, int n_in,
                              void* d_out, int out_size) {
    const float* input = (const float*)d_in[0];
    const float* W_ih  = (const float*)d_in[1];
    const float* W_hh  = (const float*)d_in[2];
    const float* b_ih  = (const float*)d_in[3];
    const float* b_hh  = (const float*)d_in[4];
    const float* fc_w  = (const float*)d_in[5];
    // d_in[6] = fc_b (cancels inside softmax)

    float* out   = (float*)d_out;
    float* out_w = out;                              // (B,T,K)
    float* out_h = out + (size_t)B_ * T_ * K_;       // (B,T,H)

    cudaFuncSetAttribute(k_xgemm, cudaFuncAttributeMaxDynamicSharedMemorySize, GX_SMEMB);
    cudaFuncSetAttribute(k_lstm,  cudaFuncAttributeMaxDynamicSharedMemorySize, L_SMEMB);

    k_alpha<<<B_, 128>>>(input, fc_w, out_w);
    k_xgemm<<<(BT_ / 64) * 8, NT_, GX_SMEMB>>>(out_w, W_ih, b_ih, b_hh);
    k_lstm<<<(B_ / MB_) * CL_, NT_, L_SMEMB>>>(W_hh, out_h);
}